// round 5
// baseline (speedup 1.0000x reference)
#include <cuda_runtime.h>
#include <stdint.h>

// YOLOv5 post-processing v4.1 (3-kernel), fixes R4 ballot-divergence hang:
//   K0: zero per-image counters
//   K1: full-chip conf computation + per-image candidate key compaction (gmem)
//   K2: per-image histogram select -> bitonic sort -> class partition ->
//       pipelined chunked bitmask NMS (sparse resolve) -> scale_coords
//
#define NANCH    15120
#define KEYCAP   15360
#define KDET     1000
#define NB       128
#define NT       1024
#define FULLM    0xFFFFFFFFu
#define CONF_THRES 0.25f
#define IOU_THRES  0.45f
#define MAX_WH     4096.0f
#define GAIN       0.5f
#define PAD_H      12.0f
#define LIM_W      1280.0f
#define LIM_H      720.0f

// Output layout (float32): boxes[128,1000,4] | scores[128,1000] | labels | valid
#define OFF_SCORES (NB * KDET * 4)
#define OFF_LABELS (OFF_SCORES + NB * KDET)
#define OFF_VALID  (OFF_LABELS + NB * KDET)

__device__ unsigned long long g_keys[NB * KEYCAP];   // 15.7 MB scratch
__device__ int g_cnt[NB];

// ---------------- K0: zero counters ----------------
__global__ void k0_init()
{
    if (threadIdx.x < NB) g_cnt[threadIdx.x] = 0;
}

// ---------------- K1: conf + candidate compaction ----------------
// grid (15, 128), block 256, 4 anchors/thread. Fixed trip count: every lane
// always reaches the ballots.
__global__ __launch_bounds__(256)
void k1_scan(const float* __restrict__ pred)
{
    const int b = blockIdx.y;
    const int t = threadIdx.x;
    const int lane = t & 31;
    const unsigned lanemask_lt = (1u << lane) - 1u;
    const float* p = pred + (size_t)b * NANCH * 8;

    #pragma unroll
    for (int j = 0; j < 4; ++j) {
        const int i = blockIdx.x * 1024 + j * 256 + t;
        bool cand = false;
        unsigned long long key = 0ull;
        if (i < NANCH) {
            const float4 v1 = __ldg((const float4*)(p + (size_t)i * 8 + 4));
            const float obj = v1.x;
            float conf = obj * v1.y;
            const float m1 = obj * v1.z;
            const float m2 = obj * v1.w;
            if (m1 > conf) conf = m1;
            if (m2 > conf) conf = m2;
            if (conf > CONF_THRES) {
                cand = true;
                key = ((unsigned long long)__float_as_uint(conf) << 32)
                    | (unsigned long long)(0xFFFFFFFFu - (unsigned)i);
            }
        }
        const unsigned mk = __ballot_sync(FULLM, cand);
        if (mk) {
            const int ldr = __ffs(mk) - 1;
            int base_;
            if (lane == ldr) base_ = atomicAdd(&g_cnt[b], __popc(mk));
            base_ = __shfl_sync(FULLM, base_, ldr);
            if (cand)
                g_keys[(size_t)b * KEYCAP + base_ + __popc(mk & lanemask_lt)] = key;
        }
    }
}

// ---------------- K2: per-image select + sort + NMS ----------------
struct Smem2 {
    unsigned long long keyarr[KEYCAP];           // 122880 B
    union {
        unsigned int hist[4096];                 // 16 KB
        float4 gbox[1024];
    } u0;
    union {
        unsigned long long keybuf[1024];         // 8 KB
        struct { float garA[1024]; unsigned int gbase[1024]; } n;
    } u1;
    unsigned long long binbuf[2048];             // 16 KB
    unsigned int aliveB[1024];
    unsigned long long wsum[32];
    unsigned int aliveW[32];
    int sCut; int cntA; int cntB;
};

__device__ __forceinline__ unsigned long long bitonic_shfl_step(
    unsigned long long v, int j, int k, int t)
{
    unsigned long long pv = __shfl_xor_sync(FULLM, v, j);
    const bool desc  = ((t & k) == 0);
    const bool lower = ((t & j) == 0);
    const bool keepmax = (lower == desc);
    const unsigned long long mx = (v > pv) ? v : pv;
    const unsigned long long mn = (v > pv) ? pv : v;
    return keepmax ? mx : mn;
}

__device__ __forceinline__ unsigned key_digit(unsigned long long key)
{
    unsigned d = ((unsigned)(key >> 32) >> 12) - 0x3E800u;
    return (d > 4095u) ? 4095u : d;
}

__device__ __forceinline__ unsigned chunk_mask(
    int k, int pp, int blo, float4 mb, float ma,
    const float4* __restrict__ gbox, const float* __restrict__ garA)
{
    const int qbase = k << 5;
    const int qlo = max(qbase, blo);
    const int qhi = min(qbase + 32, pp);
    unsigned mask = 0u;
    #pragma unroll 4
    for (int q = qlo; q < qhi; ++q) {
        const float4 qb = gbox[q];
        const float lx = fmaxf(qb.x, mb.x);
        const float ly = fmaxf(qb.y, mb.y);
        const float rx = fminf(qb.z, mb.z);
        const float ry = fminf(qb.w, mb.w);
        const float ww = fmaxf(rx - lx, 0.0f);
        const float hh = fmaxf(ry - ly, 0.0f);
        const float inter = ww * hh;
        const float iou = inter / (garA[q] + ma - inter + 1e-7f);
        if (iou > IOU_THRES) mask |= 1u << (q - qbase);
    }
    return mask;
}

__global__ __launch_bounds__(NT, 1)
void k2_nms(const float* __restrict__ pred, float* __restrict__ out)
{
    extern __shared__ unsigned char smem_raw[];
    Smem2* sm = (Smem2*)smem_raw;

    const int b = blockIdx.x;
    const int t = threadIdx.x;
    const int lane = t & 31;
    const int w = t >> 5;
    const unsigned lanemask_lt = (1u << lane) - 1u;
    const float* p = pred + (size_t)b * NANCH * 8;
    const int cnt = min(g_cnt[b], KEYCAP);

    // ---- load keys + histogram (no warp-sync ops: ragged loop is fine) ----
    #pragma unroll
    for (int j = 0; j < 4; ++j) sm->u0.hist[t + j * NT] = 0u;
    if (t == 0) { sm->sCut = 0; sm->cntA = 0; sm->cntB = 0; }
    __syncthreads();
    for (int i = t; i < cnt; i += NT) {
        const unsigned long long key = g_keys[(size_t)b * KEYCAP + i];
        sm->keyarr[i] = key;
        atomicAdd(&sm->u0.hist[key_digit(key)], 1u);
    }
    __syncthreads();

    // ---- cutoff bin via suffix scan (thread t owns bins [4t,4t+4)) ----
    const unsigned h0 = sm->u0.hist[4 * t + 0];
    const unsigned h1 = sm->u0.hist[4 * t + 1];
    const unsigned h2 = sm->u0.hist[4 * t + 2];
    const unsigned h3 = sm->u0.hist[4 * t + 3];
    const unsigned st = h0 + h1 + h2 + h3;
    unsigned long long sv = st;
    #pragma unroll
    for (int d = 1; d < 32; d <<= 1) {
        unsigned long long tmp = __shfl_down_sync(FULLM, sv, d);
        if (lane + d < 32) sv += tmp;
    }
    if (lane == 0) sm->wsum[w] = sv;
    __syncthreads();
    if (w == 0) {
        unsigned long long x = sm->wsum[lane];
        unsigned long long own = x;
        #pragma unroll
        for (int d = 1; d < 32; d <<= 1) {
            unsigned long long tmp = __shfl_down_sync(FULLM, x, d);
            if (lane + d < 32) x += tmp;
        }
        sm->wsum[lane] = x - own;    // suffix-exclusive over warps
    }
    __syncthreads();
    {
        const unsigned long long sufThread = sm->wsum[w] + (sv - st);
        if (sufThread < (unsigned long long)KDET &&
            sufThread + st >= (unsigned long long)KDET) {
            unsigned run = (unsigned)sufThread;
            int cut;
            run += h3; if (run >= KDET) cut = 4 * t + 3;
            else { run += h2; if (run >= KDET) cut = 4 * t + 2;
            else { run += h1; if (run >= KDET) cut = 4 * t + 1;
            else cut = 4 * t; } }
            sm->sCut = cut;
        }
    }
    __syncthreads();
    const unsigned cut = (unsigned)sm->sCut;
    __syncthreads();

    // ---- collect strict set + boundary bin ----
    // FIXED-TRIP loop: every lane reaches the ballots on every iteration.
    const int niter = (cnt + NT - 1) / NT;   // block-uniform
    for (int j = 0; j < niter; ++j) {
        const int i = t + j * NT;
        const bool active = (i < cnt);
        unsigned long long key = 0ull;
        unsigned d = 0u;
        if (active) { key = sm->keyarr[i]; d = key_digit(key); }
        const bool isA = active && (d > cut);
        const bool isB = active && (d == cut);
        const unsigned mA = __ballot_sync(FULLM, isA);
        const unsigned mB = __ballot_sync(FULLM, isB);
        int posA = 0, posB = 0;
        if (mA) {
            const int ldr = __ffs(mA) - 1;
            int base_;
            if (lane == ldr) base_ = atomicAdd(&sm->cntA, __popc(mA));
            base_ = __shfl_sync(FULLM, base_, ldr);
            posA = base_ + __popc(mA & lanemask_lt);
        }
        if (mB) {
            const int ldr = __ffs(mB) - 1;
            int base_;
            if (lane == ldr) base_ = atomicAdd(&sm->cntB, __popc(mB));
            base_ = __shfl_sync(FULLM, base_, ldr);
            posB = base_ + __popc(mB & lanemask_lt);
        }
        if (isA)      { if (posA < 1024) sm->u1.keybuf[posA] = key; }
        else if (isB) { if (posB < 2048) sm->binbuf[posB] = key; }
    }
    __syncthreads();

    const int C = min(sm->cntA, 1024);
    const int m = min(sm->cntB, 2048);
    const int need = max(0, min(KDET - C, m));

    // exact rank within boundary bin (keys distinct via index bits)
    for (int i = t; i < m; i += NT) {
        const unsigned long long mykey = sm->binbuf[i];
        int rank = 0;
        for (int q = 0; q < m; ++q)
            rank += (sm->binbuf[q] > mykey) ? 1 : 0;
        if (rank < need) sm->u1.keybuf[C + rank] = mykey;
    }
    if (t >= C + need) sm->u1.keybuf[t] = 0ull;
    __syncthreads();

    // ---- bitonic sort 1024 desc (hybrid shfl/smem) ----
    unsigned long long v = sm->u1.keybuf[t];
    #pragma unroll
    for (int k = 2; k <= 32; k <<= 1)
        for (int j = k >> 1; j >= 1; j >>= 1)
            v = bitonic_shfl_step(v, j, k, t);
    for (int k = 64; k <= NT; k <<= 1) {
        for (int j = k >> 1; j >= 32; j >>= 1) {
            __syncthreads();
            sm->u1.keybuf[t] = v;
            __syncthreads();
            const unsigned long long pv = sm->u1.keybuf[t ^ j];
            const bool desc  = ((t & k) == 0);
            const bool lower = ((t & j) == 0);
            const bool keepmax = (lower == desc);
            const unsigned long long mx = (v > pv) ? v : pv;
            const unsigned long long mn = (v > pv) ? pv : v;
            v = keepmax ? mx : mn;
        }
        #pragma unroll
        for (int j = 16; j >= 1; j >>= 1)
            v = bitonic_shfl_step(v, j, k, t);
    }

    // ---- decode + class partition ----
    const float score = __uint_as_float((unsigned)(v >> 32));
    float x1 = 0.f, y1 = 0.f, x2 = 0.f, y2 = 0.f;
    float ox1 = 0.f, oy1 = 0.f, ox2 = 0.f, oy2 = 0.f, ar = 0.f;
    int cls = 0;
    if (t < KDET && score > 0.0f) {
        const int idx = (int)(0xFFFFFFFFu - (unsigned)v);
        const float4 v0 = __ldg((const float4*)(p + (size_t)idx * 8));
        const float4 v1 = __ldg((const float4*)(p + (size_t)idx * 8 + 4));
        const float cx = v0.x, cy = v0.y, ww = v0.z, hh = v0.w;
        x1 = cx - ww / 2.0f; y1 = cy - hh / 2.0f;
        x2 = cx + ww / 2.0f; y2 = cy + hh / 2.0f;
        const float obj = v1.x;
        const float m0 = obj * v1.y, mm1 = obj * v1.z, mm2 = obj * v1.w;
        float best = m0; cls = 0;
        if (mm1 > best) { best = mm1; cls = 1; }
        if (mm2 > best) { best = mm2; cls = 2; }
        const float off = (float)cls * MAX_WH;
        ox1 = x1 + off; oy1 = y1 + off; ox2 = x2 + off; oy2 = y2 + off;
        ar = (ox2 - ox1) * (oy2 - oy1);   // ref: area on OFFSET boxes
    }
    const int pcls = (t < KDET && score > 0.0f) ? cls : 3;

    // packed 4x16-bit counter scan via shfl
    const unsigned long long myval = 1ull << (16 * pcls);
    unsigned long long x = myval;
    #pragma unroll
    for (int d = 1; d < 32; d <<= 1) {
        const unsigned long long y = __shfl_up_sync(FULLM, x, d);
        if (lane >= d) x += y;
    }
    __syncthreads();
    if (lane == 31) sm->wsum[w] = x;
    __syncthreads();
    if (w == 0) {
        unsigned long long z = sm->wsum[lane];
        #pragma unroll
        for (int d = 1; d < 32; d <<= 1) {
            const unsigned long long y = __shfl_up_sync(FULLM, z, d);
            if (lane >= d) z += y;
        }
        sm->wsum[lane] = z;
    }
    __syncthreads();
    const unsigned long long base = (w > 0) ? sm->wsum[w - 1] : 0ull;
    const unsigned long long incl = base + x;
    const unsigned long long tot  = sm->wsum[31];
    const unsigned long long excl = incl - myval;
    const unsigned c0 = (unsigned)(tot & 0xFFFF);
    const unsigned c1 = (unsigned)((tot >> 16) & 0xFFFF);
    const unsigned c2 = (unsigned)((tot >> 32) & 0xFFFF);
    const unsigned baseArr[4] = {0u, c0, c0 + c1, c0 + c1 + c2};
    const unsigned mybase = baseArr[pcls];
    const unsigned myrank = (unsigned)(excl >> (16 * pcls)) & 0xFFFFu;
    const unsigned mypos  = mybase + myrank;
    const unsigned base3  = c0 + c1 + c2;

    __syncthreads();
    sm->u0.gbox[mypos]    = make_float4(ox1, oy1, ox2, oy2);
    sm->u1.n.garA[mypos]  = ar;
    sm->u1.n.gbase[mypos] = mybase;
    __syncthreads();

    // ---- pipelined chunked bitmask NMS (sparse resolve) ----
    const int pp = t;
    const float4 mb = sm->u0.gbox[pp];
    const float  ma = sm->u1.n.garA[pp];
    const int    blo = (int)sm->u1.n.gbase[pp];
    bool my_dead = (pp >= (int)base3);
    const int nch = ((int)base3 + 31) >> 5;   // chunks containing live items

    unsigned mcur = (nch > 0)
        ? chunk_mask(0, pp, blo, mb, ma, sm->u0.gbox, sm->u1.n.garA) : 0u;
    for (int k = 0; k < nch; ++k) {
        unsigned mnext = 0u;
        if (w == k) {
            // sparse serial resolve: only visit alive suppressor bits.
            // q strictly increases -> terminates in <= 32 steps.
            bool aliveL = !my_dead;
            const unsigned anyk = __reduce_or_sync(FULLM, mcur);
            unsigned aliveBits = __ballot_sync(FULLM, aliveL);
            unsigned todo = anyk & aliveBits;
            while (todo) {
                const int q = __ffs(todo) - 1;
                if (lane > q && ((mcur >> q) & 1u)) aliveL = false;
                aliveBits = __ballot_sync(FULLM, aliveL);
                todo = anyk & aliveBits & (0xFFFFFFFEu << q);
            }
            if (lane == 0) sm->aliveW[k] = aliveBits;
            my_dead = !aliveL;
        } else if (w > k && k + 1 < nch) {
            mnext = chunk_mask(k + 1, pp, blo, mb, ma, sm->u0.gbox, sm->u1.n.garA);
        }
        __syncthreads();
        if (w > k) {
            const unsigned aw = sm->aliveW[k];
            if (mcur & aw) my_dead = true;
        }
        mcur = mnext;
    }
    sm->aliveB[pp] = my_dead ? 0u : 1u;
    __syncthreads();

    // ---- scale_coords + outputs ----
    if (t < KDET) {
        const int kkeep = (int)sm->aliveB[mypos];
        const float kf = kkeep ? 1.0f : 0.0f;

        const float fx1 = rintf(fminf(fmaxf((x1 - 0.0f) / GAIN, 0.0f), LIM_W));
        const float fy1 = rintf(fminf(fmaxf((y1 - PAD_H) / GAIN, 0.0f), LIM_H));
        const float fx2 = rintf(fminf(fmaxf((x2 - 0.0f) / GAIN, 0.0f), LIM_W));
        const float fy2 = rintf(fminf(fmaxf((y2 - PAD_H) / GAIN, 0.0f), LIM_H));

        ((float4*)out)[b * KDET + t] = make_float4(fx1 * kf, fy1 * kf, fx2 * kf, fy2 * kf);
        out[OFF_SCORES + b * KDET + t] = score * kf;
        out[OFF_LABELS + b * KDET + t] = (float)(kkeep ? (cls + 1) : 0);
        out[OFF_VALID  + b * KDET + t] = kf;
    }
}

extern "C" void kernel_launch(void* const* d_in, const int* in_sizes, int n_in,
                              void* d_out, int out_size)
{
    (void)in_sizes; (void)n_in; (void)out_size;
    const float* pred = (const float*)d_in[0];
    float* out = (float*)d_out;

    k0_init<<<1, NB>>>();
    k1_scan<<<dim3(15, NB), 256>>>(pred);
    cudaFuncSetAttribute(k2_nms,
                         cudaFuncAttributeMaxDynamicSharedMemorySize,
                         (int)sizeof(Smem2));
    k2_nms<<<NB, NT, sizeof(Smem2)>>>(pred, out);
}

// round 6
// speedup vs baseline: 4.3658x; 4.3658x over previous
#include <cuda_runtime.h>
#include <stdint.h>

// YOLOv5 post-processing v6 (single kernel):
//   conf->digit histogram select -> hybrid bitonic sort -> class partition
//   (padded to 32-slot boundaries) -> precomputed-bitmask NMS with per-class
//   parallel wavefront -> scale_coords.
// One block (1024 threads) per image.

#define NANCH    15120
#define KDET     1000
#define NB       128
#define NT       1024
#define NITER    15          // ceil(15120/1024)
#define FULLM    0xFFFFFFFFu
#define NSLOT    1088        // 34 chunks: 1000 items + <=62 pad + margin
#define MAXW     16          // max mask words/slot (class <=512 items; data ~333)
#define MSTRIDE  17          // maskS row stride (coprime with 32 banks)
#define CONF_THRES 0.25f
#define IOU_THRES  0.45f
#define MAX_WH     4096.0f
#define GAIN       0.5f
#define PAD_H      12.0f
#define LIM_W      1280.0f
#define LIM_H      720.0f

// Output layout (float32): boxes[128,1000,4] | scores[128,1000] | labels | valid
#define OFF_SCORES (NB * KDET * 4)
#define OFF_LABELS (OFF_SCORES + NB * KDET)
#define OFF_VALID  (OFF_LABELS + NB * KDET)

struct SmemT {
    unsigned short digitS[NANCH + 16];        // 30272 B
    unsigned int hist[4096];                  // 16384
    unsigned long long keybuf[NT];            // 8192
    unsigned long long binbuf[2048];          // 16384
    float4 gbox[NSLOT];                       // 17408
    float garA[NSLOT];                        // 4352
    unsigned int maskS[NSLOT * MSTRIDE];      // 73984
    unsigned int aliveB[NSLOT];               // 4352
    unsigned long long wsum[32];              // 256
    unsigned int aliveW[34];                  // 136
    int sCut; int cntA; int cntB;
};

__device__ __forceinline__ unsigned long long bitonic_shfl_step(
    unsigned long long v, int j, int k, int t)
{
    unsigned long long pv = __shfl_xor_sync(FULLM, v, j);
    const bool desc  = ((t & k) == 0);
    const bool lower = ((t & j) == 0);
    const bool keepmax = (lower == desc);
    const unsigned long long mx = (v > pv) ? v : pv;
    const unsigned long long mn = (v > pv) ? pv : v;
    return keepmax ? mx : mn;
}

__global__ __launch_bounds__(NT, 1)
void yolo_nms_kernel(const float* __restrict__ pred, float* __restrict__ out)
{
    extern __shared__ unsigned char smem_raw[];
    SmemT* sm = (SmemT*)smem_raw;

    const int b = blockIdx.x;
    const int t = threadIdx.x;
    const int lane = t & 31;
    const int w = t >> 5;
    const unsigned lanemask_lt = (1u << lane) - 1u;
    const float* p = pred + (size_t)b * NANCH * 8;

    // ---------------- init ----------------
    #pragma unroll
    for (int j = 0; j < 4; ++j) sm->hist[t + j * NT] = 0u;
    if (t == 0) { sm->sCut = 0; sm->cntA = 0; sm->cntB = 0; }
    __syncthreads();

    // ---------------- Phase A: conf -> digit histogram ----------------
    #pragma unroll
    for (int j = 0; j < NITER; ++j) {
        const int i = t + j * NT;
        if (i < NANCH) {
            const float4 v1 = __ldg((const float4*)(p + (size_t)i * 8 + 4));
            const float obj = v1.x;
            float conf = obj * v1.y;
            const float m1 = obj * v1.z;
            const float m2 = obj * v1.w;
            if (m1 > conf) conf = m1;
            if (m2 > conf) conf = m2;
            unsigned short sd = 0;
            if (conf > CONF_THRES) {
                unsigned d = (__float_as_uint(conf) >> 12) - 0x3E800u;
                if (d > 4095u) d = 4095u;
                atomicAdd(&sm->hist[d], 1u);
                sd = (unsigned short)(d + 1u);
            }
            sm->digitS[i] = sd;
        }
    }
    __syncthreads();

    // ---------------- cutoff bin (suffix scan; thread t owns bins 4t..) ----
    const unsigned h0 = sm->hist[4 * t + 0];
    const unsigned h1 = sm->hist[4 * t + 1];
    const unsigned h2 = sm->hist[4 * t + 2];
    const unsigned h3 = sm->hist[4 * t + 3];
    const unsigned st = h0 + h1 + h2 + h3;
    unsigned long long sv = st;
    #pragma unroll
    for (int d = 1; d < 32; d <<= 1) {
        unsigned long long tmp = __shfl_down_sync(FULLM, sv, d);
        if (lane + d < 32) sv += tmp;
    }
    if (lane == 0) sm->wsum[w] = sv;
    __syncthreads();
    if (w == 0) {
        unsigned long long x = sm->wsum[lane];
        unsigned long long own = x;
        #pragma unroll
        for (int d = 1; d < 32; d <<= 1) {
            unsigned long long tmp = __shfl_down_sync(FULLM, x, d);
            if (lane + d < 32) x += tmp;
        }
        sm->wsum[lane] = x - own;   // suffix-exclusive over warps
    }
    __syncthreads();
    {
        const unsigned long long sufThread = sm->wsum[w] + (sv - st);
        if (sufThread < (unsigned long long)KDET &&
            sufThread + st >= (unsigned long long)KDET) {
            unsigned run = (unsigned)sufThread;
            int cut;
            run += h3; if (run >= KDET) cut = 4 * t + 3;
            else { run += h2; if (run >= KDET) cut = 4 * t + 2;
            else { run += h1; if (run >= KDET) cut = 4 * t + 1;
            else cut = 4 * t; } }
            sm->sCut = cut;
        }
    }
    __syncthreads();
    const unsigned cutp1 = (unsigned)sm->sCut + 1u;
    __syncthreads();

    // ---------------- collect strict set + boundary bin (fixed trip) ----
    #pragma unroll
    for (int j = 0; j < NITER; ++j) {
        const int i = t + j * NT;
        unsigned sd = 0;
        if (i < NANCH) sd = sm->digitS[i];
        const bool isA = sd > cutp1;
        const bool isB = sd == cutp1;
        const unsigned mA = __ballot_sync(FULLM, isA);
        const unsigned mB = __ballot_sync(FULLM, isB);
        int posA = 0, posB = 0;
        if (mA) {
            const int ldr = __ffs(mA) - 1;
            int base_;
            if (lane == ldr) base_ = atomicAdd(&sm->cntA, __popc(mA));
            base_ = __shfl_sync(FULLM, base_, ldr);
            posA = base_ + __popc(mA & lanemask_lt);
        }
        if (mB) {
            const int ldr = __ffs(mB) - 1;
            int base_;
            if (lane == ldr) base_ = atomicAdd(&sm->cntB, __popc(mB));
            base_ = __shfl_sync(FULLM, base_, ldr);
            posB = base_ + __popc(mB & lanemask_lt);
        }
        if (isA || isB) {
            const float4 v1 = __ldg((const float4*)(p + (size_t)i * 8 + 4));
            const float obj = v1.x;
            float conf = obj * v1.y;
            const float m1 = obj * v1.z;
            const float m2 = obj * v1.w;
            if (m1 > conf) conf = m1;
            if (m2 > conf) conf = m2;
            const unsigned long long key =
                ((unsigned long long)__float_as_uint(conf) << 32)
                | (unsigned long long)(0xFFFFFFFFu - (unsigned)i);
            if (isA) { if (posA < 1024) sm->keybuf[posA] = key; }
            else     { if (posB < 2048) sm->binbuf[posB] = key; }
        }
    }
    __syncthreads();

    const int C = min(sm->cntA, 1024);
    const int m = min(sm->cntB, 2048);
    const int need = max(0, min(KDET - C, m));

    for (int i = t; i < m; i += NT) {
        const unsigned long long mykey = sm->binbuf[i];
        int rank = 0;
        for (int q = 0; q < m; ++q)
            rank += (sm->binbuf[q] > mykey) ? 1 : 0;
        if (rank < need) sm->keybuf[C + rank] = mykey;
    }
    if (t >= C + need) sm->keybuf[t] = 0ull;
    __syncthreads();

    // ---------------- bitonic sort 1024 desc (hybrid shfl/smem) --------
    unsigned long long v = sm->keybuf[t];
    #pragma unroll
    for (int k = 2; k <= 32; k <<= 1)
        for (int j = k >> 1; j >= 1; j >>= 1)
            v = bitonic_shfl_step(v, j, k, t);
    for (int k = 64; k <= NT; k <<= 1) {
        for (int j = k >> 1; j >= 32; j >>= 1) {
            __syncthreads();
            sm->keybuf[t] = v;
            __syncthreads();
            const unsigned long long pv = sm->keybuf[t ^ j];
            const bool desc  = ((t & k) == 0);
            const bool lower = ((t & j) == 0);
            const bool keepmax = (lower == desc);
            const unsigned long long mx = (v > pv) ? v : pv;
            const unsigned long long mn = (v > pv) ? pv : v;
            v = keepmax ? mx : mn;
        }
        #pragma unroll
        for (int j = 16; j >= 1; j >>= 1)
            v = bitonic_shfl_step(v, j, k, t);
    }

    // ---------------- decode ----------------
    const float score = __uint_as_float((unsigned)(v >> 32));
    const bool haveDet = (t < KDET) && (score > 0.0f);
    float x1 = 0.f, y1 = 0.f, x2 = 0.f, y2 = 0.f;
    float ox1 = 0.f, oy1 = 0.f, ox2 = 0.f, oy2 = 0.f, ar = 0.f;
    int cls = 0;
    if (haveDet) {
        const int idx = (int)(0xFFFFFFFFu - (unsigned)v);
        const float4 v0 = __ldg((const float4*)(p + (size_t)idx * 8));
        const float4 v1 = __ldg((const float4*)(p + (size_t)idx * 8 + 4));
        const float cx = v0.x, cy = v0.y, ww = v0.z, hh = v0.w;
        x1 = cx - ww / 2.0f; y1 = cy - hh / 2.0f;
        x2 = cx + ww / 2.0f; y2 = cy + hh / 2.0f;
        const float obj = v1.x;
        const float m0 = obj * v1.y, mm1 = obj * v1.z, mm2 = obj * v1.w;
        float best = m0; cls = 0;
        if (mm1 > best) { best = mm1; cls = 1; }
        if (mm2 > best) { best = mm2; cls = 2; }
        const float off = (float)cls * MAX_WH;
        ox1 = x1 + off; oy1 = y1 + off; ox2 = x2 + off; oy2 = y2 + off;
        ar = (ox2 - ox1) * (oy2 - oy1);   // ref: area on OFFSET boxes
    }
    const int pcls = haveDet ? cls : 3;

    // ---------------- class partition (packed shfl scan) ---------------
    const unsigned long long myval = 1ull << (16 * pcls);
    unsigned long long x = myval;
    #pragma unroll
    for (int d = 1; d < 32; d <<= 1) {
        const unsigned long long y = __shfl_up_sync(FULLM, x, d);
        if (lane >= d) x += y;
    }
    __syncthreads();
    if (lane == 31) sm->wsum[w] = x;
    __syncthreads();
    if (w == 0) {
        unsigned long long z = sm->wsum[lane];
        #pragma unroll
        for (int d = 1; d < 32; d <<= 1) {
            const unsigned long long y = __shfl_up_sync(FULLM, z, d);
            if (lane >= d) z += y;
        }
        sm->wsum[lane] = z;
    }
    __syncthreads();
    const unsigned long long basep = (w > 0) ? sm->wsum[w - 1] : 0ull;
    const unsigned long long incl = basep + x;
    const unsigned long long tot  = sm->wsum[31];
    const unsigned long long excl = incl - myval;
    const unsigned c0 = (unsigned)(tot & 0xFFFF);
    const unsigned c1 = (unsigned)((tot >> 16) & 0xFFFF);
    const unsigned c2 = (unsigned)((tot >> 32) & 0xFFFF);
    // padded class bases (32-aligned)
    const unsigned b1p = (c0 + 31u) & ~31u;
    const unsigned b2p = b1p + ((c1 + 31u) & ~31u);
    const unsigned Tpad = b2p + c2;
    const unsigned baseArr[4] = {0u, b1p, b2p, 0u};
    const unsigned mybase = baseArr[pcls];
    const unsigned myrank = (unsigned)(excl >> (16 * pcls)) & 0xFFFFu;
    const unsigned mypos  = mybase + myrank;    // valid only if haveDet
    const int nsteps = max(max(((int)c0 + 31) >> 5, ((int)c1 + 31) >> 5),
                           ((int)c2 + 31) >> 5);

    // ---------------- scatter (pads stay dead) -------------------------
    __syncthreads();
    for (int slot = t; slot < NSLOT; slot += NT) {
        sm->gbox[slot] = make_float4(0.f, 0.f, 0.f, 0.f);
        sm->garA[slot] = 0.f;
        sm->aliveB[slot] = 0u;
    }
    __syncthreads();
    if (haveDet) {
        sm->gbox[mypos] = make_float4(ox1, oy1, ox2, oy2);
        sm->garA[mypos] = ar;
        sm->aliveB[mypos] = 1u;
    }
    __syncthreads();

    // ---------------- Phase 1: all suppression masks (parallel) --------
    for (int slot = t; slot < (int)Tpad; slot += NT) {
        if (!sm->aliveB[slot]) continue;
        const int scls = (slot >= (int)b2p) ? 2 : (slot >= (int)b1p) ? 1 : 0;
        const int fcj = (scls == 2) ? ((int)b2p >> 5)
                      : (scls == 1) ? ((int)b1p >> 5) : 0;
        const int jp = slot >> 5;
        const float4 mb = sm->gbox[slot];
        const float  ma = sm->garA[slot];
        for (int k = 0; k <= jp - fcj; ++k) {
            const int qbase = (fcj + k) << 5;
            const int qhi = min(qbase + 32, slot);
            unsigned mask = 0u;
            #pragma unroll 4
            for (int q = qbase; q < qhi; ++q) {
                const float4 qb = sm->gbox[q];
                const float lx = fmaxf(qb.x, mb.x);
                const float ly = fmaxf(qb.y, mb.y);
                const float rx = fminf(qb.z, mb.z);
                const float ry = fminf(qb.w, mb.w);
                const float ww = fmaxf(rx - lx, 0.0f);
                const float hh = fmaxf(ry - ly, 0.0f);
                const float inter = ww * hh;
                // iou > T  <=>  inter > T*(aq + ma - inter + 1e-7)  (den > 0)
                if (inter > IOU_THRES * (sm->garA[q] + ma - inter + 1e-7f))
                    mask |= 1u << (q - qbase);
            }
            sm->maskS[slot * MSTRIDE + k] = mask;
        }
    }
    __syncthreads();

    // ---------------- Phase 2: per-class parallel wavefront ------------
    // chunk j resolver: warp j (j<=31); chunk 32 -> warp 31; chunk 33 -> warp 30.
    const int nchTot = ((int)Tpad + 31) >> 5;
    for (int s = 0; s < nsteps; ++s) {
        // resolve my chunk(s)
        #pragma unroll
        for (int e = 0; e < 2; ++e) {
            int j = -1;
            if (e == 0) j = w;
            else if (w == 31) j = 32;
            else if (w == 30) j = 33;
            if (j >= 0 && j < nchTot) {
                const int jb = j << 5;
                const int jcls = (jb >= (int)b2p) ? 2 : (jb >= (int)b1p) ? 1 : 0;
                const int fcj = (jcls == 2) ? ((int)b2p >> 5)
                              : (jcls == 1) ? ((int)b1p >> 5) : 0;
                if (j - fcj == s) {
                    const int slot = jb + lane;
                    const unsigned mask = sm->maskS[slot * MSTRIDE + s];
                    bool aliveL = sm->aliveB[slot] != 0u;
                    const unsigned anyk = __reduce_or_sync(FULLM, mask);
                    unsigned aliveBits = __ballot_sync(FULLM, aliveL);
                    unsigned todo = anyk & aliveBits;
                    while (todo) {
                        const int q = __ffs(todo) - 1;
                        if (lane > q && ((mask >> q) & 1u)) aliveL = false;
                        aliveBits = __ballot_sync(FULLM, aliveL);
                        todo = anyk & aliveBits & (0xFFFFFFFEu << q);
                    }
                    if (lane == 0) sm->aliveW[j] = aliveBits;
                    sm->aliveB[slot] = aliveL ? 1u : 0u;
                }
            }
        }
        __syncthreads();
        // apply resolved chunk of step s to later chunks of same class
        for (int slot = t; slot < (int)Tpad; slot += NT) {
            if (!sm->aliveB[slot]) continue;
            const int scls = (slot >= (int)b2p) ? 2 : (slot >= (int)b1p) ? 1 : 0;
            const int fcj = (scls == 2) ? ((int)b2p >> 5)
                          : (scls == 1) ? ((int)b1p >> 5) : 0;
            const int sp = (slot >> 5) - fcj;
            if (s < sp) {
                if (sm->maskS[slot * MSTRIDE + s] & sm->aliveW[fcj + s])
                    sm->aliveB[slot] = 0u;
            }
        }
        __syncthreads();
    }

    // ---------------- scale_coords + outputs ---------------------------
    if (t < KDET) {
        const int kkeep = haveDet ? (int)sm->aliveB[mypos] : 0;
        const float kf = kkeep ? 1.0f : 0.0f;

        const float fx1 = rintf(fminf(fmaxf((x1 - 0.0f) / GAIN, 0.0f), LIM_W));
        const float fy1 = rintf(fminf(fmaxf((y1 - PAD_H) / GAIN, 0.0f), LIM_H));
        const float fx2 = rintf(fminf(fmaxf((x2 - 0.0f) / GAIN, 0.0f), LIM_W));
        const float fy2 = rintf(fminf(fmaxf((y2 - PAD_H) / GAIN, 0.0f), LIM_H));

        ((float4*)out)[b * KDET + t] = make_float4(fx1 * kf, fy1 * kf, fx2 * kf, fy2 * kf);
        out[OFF_SCORES + b * KDET + t] = score * kf;
        out[OFF_LABELS + b * KDET + t] = (float)(kkeep ? (cls + 1) : 0);
        out[OFF_VALID  + b * KDET + t] = kf;
    }
}

extern "C" void kernel_launch(void* const* d_in, const int* in_sizes, int n_in,
                              void* d_out, int out_size)
{
    (void)in_sizes; (void)n_in; (void)out_size;
    const float* pred = (const float*)d_in[0];
    float* out = (float*)d_out;

    cudaFuncSetAttribute(yolo_nms_kernel,
                         cudaFuncAttributeMaxDynamicSharedMemorySize,
                         (int)sizeof(SmemT));
    yolo_nms_kernel<<<NB, NT, sizeof(SmemT)>>>(pred, out);
}

// round 7
// speedup vs baseline: 4.6544x; 1.0661x over previous
#include <cuda_runtime.h>
#include <stdint.h>

// YOLOv5 post-processing v7 (single kernel):
//   single-pass conf->keys(smem)+histogram -> counting-sort by 4096 bins ->
//   tiny per-bin insertion sorts -> class partition -> precomputed-bitmask NMS
//   with per-class parallel wavefront -> scale_coords.
// One block (1024 threads) per image.

#define NANCH    15120
#define KDET     1000
#define NB       128
#define NT       1024
#define NITER    15          // ceil(15120/1024)
#define FULLM    0xFFFFFFFFu
#define NSLOT    1088
#define MSTRIDE  17
#define CONF_THRES 0.25f
#define IOU_THRES  0.45f
#define MAX_WH     4096.0f
#define GAIN       0.5f
#define PAD_H      12.0f
#define LIM_W      1280.0f
#define LIM_H      720.0f

// Output layout (float32): boxes[128,1000,4] | scores[128,1000] | labels | valid
#define OFF_SCORES (NB * KDET * 4)
#define OFF_LABELS (OFF_SCORES + NB * KDET)
#define OFF_VALID  (OFF_LABELS + NB * KDET)

struct SmemT {
    union {
        unsigned long long keyarr[15232];            // 121856 B (phase A..scatter)
        struct {                                     // NMS overlay (after scatter)
            float4 gbox[NSLOT];                      // 17408
            float garA[NSLOT];                       // 4352
            unsigned int maskS[NSLOT * MSTRIDE];     // 73984
            unsigned int aliveB[NSLOT];              // 4352
        } n;
    } u;
    unsigned int hist[4096];        // histogram -> scatter cursor (start..end)
    unsigned int binstart[4096];    // saved descending segment starts
    unsigned long long sortbuf[2048];
    unsigned long long wsum[32];
    unsigned int aliveW[34];
    int cntK;
};

__global__ __launch_bounds__(NT, 1)
void yolo_nms_kernel(const float* __restrict__ pred, float* __restrict__ out)
{
    extern __shared__ unsigned char smem_raw[];
    SmemT* sm = (SmemT*)smem_raw;

    const int b = blockIdx.x;
    const int t = threadIdx.x;
    const int lane = t & 31;
    const int w = t >> 5;
    const unsigned lanemask_lt = (1u << lane) - 1u;
    const float* p = pred + (size_t)b * NANCH * 8;
    const float4* prow = (const float4*)p;   // row i: prow[2i] = xywh, prow[2i+1] = obj/cls

    // ---------------- init ----------------
    #pragma unroll
    for (int j = 0; j < 4; ++j) sm->hist[t + j * NT] = 0u;
    if (t == 0) sm->cntK = 0;
    __syncthreads();

    // ------- Phase A: single pass: conf -> key in smem + histogram -------
    // key = conf_bits<<32 | ((0x3FFF - i)<<2 | cls): desc conf, asc index ties.
    {
        float4 vc = (t < NANCH) ? __ldg(prow + 2 * t + 1)
                                : make_float4(0.f, 0.f, 0.f, 0.f);
        #pragma unroll
        for (int j = 0; j < NITER; ++j) {
            const int i = t + j * NT;
            const int inx = i + NT;
            float4 vn = make_float4(0.f, 0.f, 0.f, 0.f);
            if (j < NITER - 1 && inx < NANCH) vn = __ldg(prow + 2 * inx + 1);

            bool cand = false;
            unsigned long long key = 0ull;
            if (i < NANCH) {
                const float obj = vc.x;
                float conf = obj * vc.y; int cls = 0;
                const float m1 = obj * vc.z;
                const float m2 = obj * vc.w;
                if (m1 > conf) { conf = m1; cls = 1; }
                if (m2 > conf) { conf = m2; cls = 2; }
                if (conf > CONF_THRES) {
                    cand = true;
                    const unsigned cb = __float_as_uint(conf);
                    key = ((unsigned long long)cb << 32)
                        | (unsigned long long)(((0x3FFFu - (unsigned)i) << 2) | (unsigned)cls);
                    unsigned d = (cb >> 12) - 0x3E800u;
                    if (d > 4095u) d = 4095u;
                    atomicAdd(&sm->hist[d], 1u);
                }
            }
            const unsigned mk = __ballot_sync(FULLM, cand);
            if (mk) {
                const int ldr = __ffs(mk) - 1;
                int base_;
                if (lane == ldr) base_ = atomicAdd(&sm->cntK, __popc(mk));
                base_ = __shfl_sync(FULLM, base_, ldr);
                if (cand) sm->u.keyarr[base_ + __popc(mk & lanemask_lt)] = key;
            }
            vc = vn;
        }
    }
    __syncthreads();
    const int cntK = sm->cntK;

    // ------- suffix scan: hist -> descending segment starts -------
    const unsigned h0 = sm->hist[4 * t + 0];
    const unsigned h1 = sm->hist[4 * t + 1];
    const unsigned h2 = sm->hist[4 * t + 2];
    const unsigned h3 = sm->hist[4 * t + 3];
    const unsigned st = h0 + h1 + h2 + h3;
    unsigned long long sv = st;
    #pragma unroll
    for (int d = 1; d < 32; d <<= 1) {
        unsigned long long tmp = __shfl_down_sync(FULLM, sv, d);
        if (lane + d < 32) sv += tmp;
    }
    if (lane == 0) sm->wsum[w] = sv;
    __syncthreads();
    if (w == 0) {
        unsigned long long x = sm->wsum[lane];
        unsigned long long own = x;
        #pragma unroll
        for (int d = 1; d < 32; d <<= 1) {
            unsigned long long tmp = __shfl_down_sync(FULLM, x, d);
            if (lane + d < 32) x += tmp;
        }
        sm->wsum[lane] = x - own;   // suffix-exclusive over warps
    }
    __syncthreads();
    {
        const unsigned sufThread = (unsigned)(sm->wsum[w] + (sv - st)); // keys in bins > 4t+3
        const unsigned s3 = sufThread;
        const unsigned s2 = s3 + h3;
        const unsigned s1 = s2 + h2;
        const unsigned s0 = s1 + h1;
        sm->hist[4 * t + 0] = s0; sm->binstart[4 * t + 0] = s0;
        sm->hist[4 * t + 1] = s1; sm->binstart[4 * t + 1] = s1;
        sm->hist[4 * t + 2] = s2; sm->binstart[4 * t + 2] = s2;
        sm->hist[4 * t + 3] = s3; sm->binstart[4 * t + 3] = s3;
    }
    sm->sortbuf[t] = 0ull;
    sm->sortbuf[t + NT] = 0ull;
    __syncthreads();

    // ------- counting-sort scatter (ranks >= 2048 irrelevant, dropped) ----
    for (int i = t; i < cntK; i += NT) {
        const unsigned long long key = sm->u.keyarr[i];
        unsigned d = ((unsigned)(key >> 32) >> 12) - 0x3E800u;
        if (d > 4095u) d = 4095u;
        const unsigned pos = atomicAdd(&sm->hist[d], 1u);
        if (pos < 2048u) sm->sortbuf[pos] = key;
    }
    __syncthreads();

    // ------- per-bin insertion sort (desc) for bins intersecting [0,KDET) --
    #pragma unroll
    for (int e = 0; e < 4; ++e) {
        const int d = t + e * NT;
        const int s = (int)sm->binstart[d];
        if (s < KDET) {
            const int en = min((int)sm->hist[d], 2048);
            for (int i = s + 1; i < en; ++i) {
                const unsigned long long key = sm->sortbuf[i];
                int jj = i - 1;
                while (jj >= s && sm->sortbuf[jj] < key) {
                    sm->sortbuf[jj + 1] = sm->sortbuf[jj];
                    --jj;
                }
                sm->sortbuf[jj + 1] = key;
            }
        }
    }
    __syncthreads();

    // ---------------- decode ----------------
    const unsigned long long v = sm->sortbuf[t];
    const float score = __uint_as_float((unsigned)(v >> 32));
    const bool haveDet = (t < KDET) && (score > 0.0f);
    float x1 = 0.f, y1 = 0.f, x2 = 0.f, y2 = 0.f;
    float ox1 = 0.f, oy1 = 0.f, ox2 = 0.f, oy2 = 0.f, ar = 0.f;
    int cls = 0;
    if (haveDet) {
        const unsigned lo = (unsigned)v;
        cls = (int)(lo & 3u);
        const int idx = (int)(0x3FFFu - (lo >> 2));
        const float4 v0 = __ldg(prow + 2 * idx);
        const float cx = v0.x, cy = v0.y, ww = v0.z, hh = v0.w;
        x1 = cx - ww / 2.0f; y1 = cy - hh / 2.0f;
        x2 = cx + ww / 2.0f; y2 = cy + hh / 2.0f;
        const float off = (float)cls * MAX_WH;
        ox1 = x1 + off; oy1 = y1 + off; ox2 = x2 + off; oy2 = y2 + off;
        ar = (ox2 - ox1) * (oy2 - oy1);   // ref: area on OFFSET boxes
    }
    const int pcls = haveDet ? cls : 3;

    // ---------------- class partition (packed shfl scan) ---------------
    const unsigned long long myval = 1ull << (16 * pcls);
    unsigned long long x = myval;
    #pragma unroll
    for (int d = 1; d < 32; d <<= 1) {
        const unsigned long long y = __shfl_up_sync(FULLM, x, d);
        if (lane >= d) x += y;
    }
    __syncthreads();
    if (lane == 31) sm->wsum[w] = x;
    __syncthreads();
    if (w == 0) {
        unsigned long long z = sm->wsum[lane];
        #pragma unroll
        for (int d = 1; d < 32; d <<= 1) {
            const unsigned long long y = __shfl_up_sync(FULLM, z, d);
            if (lane >= d) z += y;
        }
        sm->wsum[lane] = z;
    }
    __syncthreads();
    const unsigned long long basep = (w > 0) ? sm->wsum[w - 1] : 0ull;
    const unsigned long long incl = basep + x;
    const unsigned long long tot  = sm->wsum[31];
    const unsigned long long excl = incl - myval;
    const unsigned c0 = (unsigned)(tot & 0xFFFF);
    const unsigned c1 = (unsigned)((tot >> 16) & 0xFFFF);
    const unsigned c2 = (unsigned)((tot >> 32) & 0xFFFF);
    const unsigned b1p = (c0 + 31u) & ~31u;                 // padded bases
    const unsigned b2p = b1p + ((c1 + 31u) & ~31u);
    const unsigned Tpad = b2p + c2;
    const unsigned baseArr[4] = {0u, b1p, b2p, 0u};
    const unsigned mybase = baseArr[pcls];
    const unsigned myrank = (unsigned)(excl >> (16 * pcls)) & 0xFFFFu;
    const unsigned mypos  = mybase + myrank;    // valid only if haveDet
    const int nsteps = max(max(((int)c0 + 31) >> 5, ((int)c1 + 31) >> 5),
                           ((int)c2 + 31) >> 5);

    // ---------------- scatter into NMS arrays (overlay on keyarr) -------
    __syncthreads();
    for (int slot = t; slot < NSLOT; slot += NT) {
        sm->u.n.gbox[slot] = make_float4(0.f, 0.f, 0.f, 0.f);
        sm->u.n.garA[slot] = 0.f;
        sm->u.n.aliveB[slot] = 0u;
    }
    __syncthreads();
    if (haveDet) {
        sm->u.n.gbox[mypos] = make_float4(ox1, oy1, ox2, oy2);
        sm->u.n.garA[mypos] = ar;
        sm->u.n.aliveB[mypos] = 1u;
    }
    __syncthreads();

    // ---------------- Phase 1: all suppression masks (parallel) --------
    for (int slot = t; slot < (int)Tpad; slot += NT) {
        if (!sm->u.n.aliveB[slot]) continue;
        const int scls = (slot >= (int)b2p) ? 2 : (slot >= (int)b1p) ? 1 : 0;
        const int fcj = (scls == 2) ? ((int)b2p >> 5)
                      : (scls == 1) ? ((int)b1p >> 5) : 0;
        const int jp = slot >> 5;
        const float4 mb = sm->u.n.gbox[slot];
        const float  ma = sm->u.n.garA[slot];
        for (int k = 0; k <= jp - fcj; ++k) {
            const int qbase = (fcj + k) << 5;
            const int qhi = min(qbase + 32, slot);
            unsigned mask = 0u;
            #pragma unroll 4
            for (int q = qbase; q < qhi; ++q) {
                const float4 qb = sm->u.n.gbox[q];
                const float lx = fmaxf(qb.x, mb.x);
                const float ly = fmaxf(qb.y, mb.y);
                const float rx = fminf(qb.z, mb.z);
                const float ry = fminf(qb.w, mb.w);
                const float ww = fmaxf(rx - lx, 0.0f);
                const float hh = fmaxf(ry - ly, 0.0f);
                const float inter = ww * hh;
                // iou > T  <=>  inter > T*(aq + ma - inter + 1e-7)  (den > 0)
                if (inter > IOU_THRES * (sm->u.n.garA[q] + ma - inter + 1e-7f))
                    mask |= 1u << (q - qbase);
            }
            sm->u.n.maskS[slot * MSTRIDE + k] = mask;
        }
    }
    __syncthreads();

    // ---------------- Phase 2: per-class parallel wavefront ------------
    const int nchTot = ((int)Tpad + 31) >> 5;
    for (int s = 0; s < nsteps; ++s) {
        #pragma unroll
        for (int e = 0; e < 2; ++e) {
            int j = -1;
            if (e == 0) j = w;
            else if (w == 31) j = 32;
            else if (w == 30) j = 33;
            if (j >= 0 && j < nchTot) {
                const int jb = j << 5;
                const int jcls = (jb >= (int)b2p) ? 2 : (jb >= (int)b1p) ? 1 : 0;
                const int fcj = (jcls == 2) ? ((int)b2p >> 5)
                              : (jcls == 1) ? ((int)b1p >> 5) : 0;
                if (j - fcj == s) {
                    const int slot = jb + lane;
                    const unsigned mask = sm->u.n.maskS[slot * MSTRIDE + s];
                    bool aliveL = sm->u.n.aliveB[slot] != 0u;
                    const unsigned anyk = __reduce_or_sync(FULLM, mask);
                    unsigned aliveBits = __ballot_sync(FULLM, aliveL);
                    unsigned todo = anyk & aliveBits;
                    while (todo) {
                        const int q = __ffs(todo) - 1;
                        if (lane > q && ((mask >> q) & 1u)) aliveL = false;
                        aliveBits = __ballot_sync(FULLM, aliveL);
                        todo = anyk & aliveBits & (0xFFFFFFFEu << q);
                    }
                    if (lane == 0) sm->aliveW[j] = aliveBits;
                    sm->u.n.aliveB[slot] = aliveL ? 1u : 0u;
                }
            }
        }
        __syncthreads();
        for (int slot = t; slot < (int)Tpad; slot += NT) {
            if (!sm->u.n.aliveB[slot]) continue;
            const int scls = (slot >= (int)b2p) ? 2 : (slot >= (int)b1p) ? 1 : 0;
            const int fcj = (scls == 2) ? ((int)b2p >> 5)
                          : (scls == 1) ? ((int)b1p >> 5) : 0;
            const int sp = (slot >> 5) - fcj;
            if (s < sp) {
                if (sm->u.n.maskS[slot * MSTRIDE + s] & sm->aliveW[fcj + s])
                    sm->u.n.aliveB[slot] = 0u;
            }
        }
        __syncthreads();
    }

    // ---------------- scale_coords + outputs ---------------------------
    if (t < KDET) {
        const int kkeep = haveDet ? (int)sm->u.n.aliveB[mypos] : 0;
        const float kf = kkeep ? 1.0f : 0.0f;

        const float fx1 = rintf(fminf(fmaxf((x1 - 0.0f) / GAIN, 0.0f), LIM_W));
        const float fy1 = rintf(fminf(fmaxf((y1 - PAD_H) / GAIN, 0.0f), LIM_H));
        const float fx2 = rintf(fminf(fmaxf((x2 - 0.0f) / GAIN, 0.0f), LIM_W));
        const float fy2 = rintf(fminf(fmaxf((y2 - PAD_H) / GAIN, 0.0f), LIM_H));

        ((float4*)out)[b * KDET + t] = make_float4(fx1 * kf, fy1 * kf, fx2 * kf, fy2 * kf);
        out[OFF_SCORES + b * KDET + t] = score * kf;
        out[OFF_LABELS + b * KDET + t] = (float)(kkeep ? (cls + 1) : 0);
        out[OFF_VALID  + b * KDET + t] = kf;
    }
}

extern "C" void kernel_launch(void* const* d_in, const int* in_sizes, int n_in,
                              void* d_out, int out_size)
{
    (void)in_sizes; (void)n_in; (void)out_size;
    const float* pred = (const float*)d_in[0];
    float* out = (float*)d_out;

    cudaFuncSetAttribute(yolo_nms_kernel,
                         cudaFuncAttributeMaxDynamicSharedMemorySize,
                         (int)sizeof(SmemT));
    yolo_nms_kernel<<<NB, NT, sizeof(SmemT)>>>(pred, out);
}